// round 2
// baseline (speedup 1.0000x reference)
#include <cuda_runtime.h>

#define BATCH   1024
#define WDIM    256
#define HDIM    256
#define DEPTH   8
#define HMAX    256          // worst-case hull size (expected ~8)
#define EVAL_CTAS 128        // 2 branches x 64 w-chunks, all co-resident (<148)
#define WPC     4            // w rows per eval CTA

// Static device scratch (allocation-free rule): hulls, per-level keys, barrier counters.
__device__ float2   g_hull[2][DEPTH][WDIM][HMAX];   // (m, b) per hull line
__device__ int      g_cnt[2][DEPTH][WDIM];
__device__ unsigned g_qkey[2][DEPTH + 1][BATCH];
__device__ int      g_bar[DEPTH + 1];

// Monotone float <-> uint key (uint order == float order), finite floats only.
__device__ __forceinline__ unsigned fkey(float f) {
    unsigned u = __float_as_uint(f);
    return (u & 0x80000000u) ? ~u : (u | 0x80000000u);
}
__device__ __forceinline__ float funkey(unsigned k) {
    unsigned u = (k & 0x80000000u) ? (k & 0x7FFFFFFFu) : ~k;
    return __uint_as_float(u);
}

__global__ void init_kernel() {
    int i = blockIdx.x * blockDim.x + threadIdx.x;
    if (i < 2 * (DEPTH + 1) * BATCH)
        ((unsigned*)g_qkey)[i] = 0xFFFFFFFFu;   // key(+NaN) > key(any finite)
    if (i < DEPTH + 1)
        g_bar[i] = 0;
}

// Crossing-point comparator: is candidate A (x = nA/dA) strictly before B?
// d == 0 encodes x = -inf (equal-slope line strictly above current).
__device__ __forceinline__ bool frac_less(float nA, float dA, float nB, float dB) {
    if (dA == 0.f && dB == 0.f) return nA < nB;      // more-above line wins
    if (dA == 0.f) return true;
    if (dB == 0.f) return false;
    double l = (double)nA * (double)dB;
    double r = (double)nB * (double)dA;
    if (l != r) return l < r;
    return dA > dB;                                  // tie: take steeper step
}

// One warp per envelope (branch, d, w): gift-wrap the upper envelope of 256 lines.
__global__ void __launch_bounds__(256) hull_kernel(
    const float* __restrict__ M1, const float* __restrict__ B1,
    const float* __restrict__ M2, const float* __restrict__ B2) {
    int gw   = (blockIdx.x * blockDim.x + threadIdx.x) >> 5;   // 0..4095
    int lane = threadIdx.x & 31;
    int branch = gw >> 11;
    int d      = (gw >> 8) & 7;
    int w      = gw & 255;

    const float* Mp = (branch ? M2 : M1) + (size_t)((d << 8) + w) * HDIM;
    const float* Bp = (branch ? B2 : B1) + (size_t)((d << 8) + w) * HDIM;

    float m[8], b[8];
#pragma unroll
    for (int k = 0; k < 8; k++) {
        int h = lane + (k << 5);
        m[k] = Mp[h];
        b[k] = Bp[h];
    }

    // Start line: min slope, tie-break max intercept (dominates as q -> -inf).
    float mc = m[0], bc = b[0];
#pragma unroll
    for (int k = 1; k < 8; k++)
        if (m[k] < mc || (m[k] == mc && b[k] > bc)) { mc = m[k]; bc = b[k]; }
#pragma unroll
    for (int o = 16; o; o >>= 1) {
        float om = __shfl_xor_sync(0xFFFFFFFFu, mc, o);
        float ob = __shfl_xor_sync(0xFFFFFFFFu, bc, o);
        if (om < mc || (om == mc && ob > bc)) { mc = om; bc = ob; }
    }
    // Force uniformity
    mc = __shfl_sync(0xFFFFFFFFu, mc, 0);
    bc = __shfl_sync(0xFFFFFFFFu, bc, 0);

    float2* hp = &g_hull[branch][d][w][0];
    int cnt = 0;
    for (int step = 0; step < HMAX; ++step) {
        if (lane == 0) hp[cnt] = make_float2(mc, bc);
        cnt++;

        // Candidate = line overtaking (mc, bc) soonest going right.
        float bn = 0.f, bd = -1.f, bm = 0.f, bb = 0.f;   // bd < 0 => invalid
#pragma unroll
        for (int k = 0; k < 8; k++) {
            float dj = m[k] - mc;
            float nj = bc - b[k];
            bool valid = (dj > 0.f) || (dj == 0.f && nj < 0.f);
            if (valid && (bd < 0.f || frac_less(nj, dj, bn, bd))) {
                bn = nj; bd = dj; bm = m[k]; bb = b[k];
            }
        }
#pragma unroll
        for (int o = 16; o; o >>= 1) {
            float on = __shfl_xor_sync(0xFFFFFFFFu, bn, o);
            float od = __shfl_xor_sync(0xFFFFFFFFu, bd, o);
            float om = __shfl_xor_sync(0xFFFFFFFFu, bm, o);
            float ob = __shfl_xor_sync(0xFFFFFFFFu, bb, o);
            if (od >= 0.f && (bd < 0.f || frac_less(on, od, bn, bd))) {
                bn = on; bd = od; bm = om; bb = ob;
            }
        }
        // Broadcast lane 0's winner -> uniform control flow guaranteed.
        bd = __shfl_sync(0xFFFFFFFFu, bd, 0);
        bm = __shfl_sync(0xFFFFFFFFu, bm, 0);
        bb = __shfl_sync(0xFFFFFFFFu, bb, 0);
        if (bd < 0.f) break;
        mc = bm; bc = bb;
    }
    if (lane == 0) g_cnt[branch][d][w] = cnt;
}

// Persistent eval: 128 CTAs, 8 layers with software grid barrier between them.
__global__ void __launch_bounds__(256, 1) eval_kernel(
    const float* __restrict__ val, float* __restrict__ out) {
    const int t      = threadIdx.x;
    const int branch = blockIdx.x >> 6;
    const int wbase  = (blockIdx.x & 63) * WPC;

    float q[4];
#pragma unroll
    for (int i = 0; i < 4; i++) q[i] = val[t + (i << 8)];

    for (int d = 0; d < DEPTH; ++d) {
        if (d > 0) {
#pragma unroll
            for (int i = 0; i < 4; i++)
                q[i] = funkey(g_qkey[branch][d][t + (i << 8)]);
        }

        float vmin[4] = {3.4e38f, 3.4e38f, 3.4e38f, 3.4e38f};
        for (int wo = 0; wo < WPC; ++wo) {
            int w = wbase + wo;
            int cnt = g_cnt[branch][d][w];
            const float2* hp = &g_hull[branch][d][w][0];
            float vmax[4] = {-3.4e38f, -3.4e38f, -3.4e38f, -3.4e38f};
            for (int k = 0; k < cnt; k++) {
                float2 l = hp[k];   // broadcast load: whole warp same address
#pragma unroll
                for (int i = 0; i < 4; i++)
                    vmax[i] = fmaxf(vmax[i], fmaf(q[i], l.x, l.y));
            }
#pragma unroll
            for (int i = 0; i < 4; i++) vmin[i] = fminf(vmin[i], vmax[i]);
        }
#pragma unroll
        for (int i = 0; i < 4; i++)
            atomicMin(&g_qkey[branch][d + 1][t + (i << 8)], fkey(vmin[i]));

        // Grid-wide barrier, phase d (counters zeroed each launch by init_kernel).
        __syncthreads();
        if (t == 0) {
            __threadfence();                         // publish my atomicMins
            atomicAdd(&g_bar[d], 1);
            while (*((volatile int*)&g_bar[d]) < EVAL_CTAS) { }
            __threadfence();                         // acquire others' results
        }
        __syncthreads();
    }

    // Decode: one CTA per branch writes the outputs.
    if ((blockIdx.x & 63) == 0) {
#pragma unroll
        for (int i = 0; i < 4; i++) {
            int bi = t + (i << 8);
            out[branch * BATCH + bi] = funkey(g_qkey[branch][DEPTH][bi]);
        }
    }
}

extern "C" void kernel_launch(void* const* d_in, const int* in_sizes, int n_in,
                              void* d_out, int out_size) {
    const float* val = (const float*)d_in[0];
    const float* M1  = (const float*)d_in[1];
    const float* B1  = (const float*)d_in[2];
    const float* M2  = (const float*)d_in[3];
    const float* B2  = (const float*)d_in[4];
    float* out = (float*)d_out;

    init_kernel<<<(2 * (DEPTH + 1) * BATCH + 255) / 256, 256>>>();
    hull_kernel<<<(2 * DEPTH * WDIM * 32) / 256, 256>>>(M1, B1, M2, B2);
    eval_kernel<<<EVAL_CTAS, 256>>>(val, out);
}

// round 3
// speedup vs baseline: 2.8858x; 2.8858x over previous
#include <cuda_runtime.h>

#define BATCH   1024
#define WDIM    256
#define HDIM    256
#define DEPTH   8
#define HMAX    256     // absolute worst-case hull size
#define HC      20      // compact fast-path hull cap (Gaussian data: ~6-10 lines)

#define F_INF   __int_as_float(0x7F800000)

// Static device scratch (allocation-free rule).
__device__ float2 g_hull [2][DEPTH][WDIM][HMAX];  // full hulls (rare fallback)
__device__ float2 g_hullc[2][DEPTH][HC][WDIM];    // compact, slot-major (coalesced)
__device__ int    g_cnt  [2][DEPTH][WDIM];

// ───────────────────────── hull kernel ─────────────────────────
// One warp per envelope (branch, d, w): gift-wrap the upper envelope of the
// 256 lines y = m*q + b. Pure fp32: crossings via fast divide.
__global__ void __launch_bounds__(256) hull_kernel(
    const float* __restrict__ M1, const float* __restrict__ B1,
    const float* __restrict__ M2, const float* __restrict__ B2) {
    const int gw     = (blockIdx.x * blockDim.x + threadIdx.x) >> 5;  // 0..4095
    const int lane   = threadIdx.x & 31;
    const int branch = gw >> 11;
    const int d      = (gw >> 8) & 7;
    const int w      = gw & 255;

    const float* Mp = (branch ? M2 : M1) + (size_t)((d << 8) + w) * HDIM;
    const float* Bp = (branch ? B2 : B1) + (size_t)((d << 8) + w) * HDIM;

    float m[8], b[8];
#pragma unroll
    for (int k = 0; k < 8; k++) {
        m[k] = Mp[lane + (k << 5)];
        b[k] = Bp[lane + (k << 5)];
    }

    // Start: min slope, tie-break max intercept (dominates as q -> -inf).
    float mc = m[0], bc = b[0];
#pragma unroll
    for (int k = 1; k < 8; k++)
        if (m[k] < mc || (m[k] == mc && b[k] > bc)) { mc = m[k]; bc = b[k]; }
#pragma unroll
    for (int o = 16; o; o >>= 1) {
        float om = __shfl_xor_sync(0xFFFFFFFFu, mc, o);
        float ob = __shfl_xor_sync(0xFFFFFFFFu, bc, o);
        if (om < mc || (om == mc && ob > bc)) { mc = om; bc = ob; }
    }
    mc = __shfl_sync(0xFFFFFFFFu, mc, 0);
    bc = __shfl_sync(0xFFFFFFFFu, bc, 0);

    int cnt = 0;
    for (int step = 0; step < HMAX; ++step) {
        if (lane == 0) {
            g_hull[branch][d][w][cnt] = make_float2(mc, bc);
            if (cnt < HC) g_hullc[branch][d][cnt][w] = make_float2(mc, bc);
        }
        cnt++;

        // Candidate = valid line with the smallest crossing point going right.
        float bx = F_INF, bm = 0.f, bb = 0.f;
#pragma unroll
        for (int k = 0; k < 8; k++) {
            float dj = m[k] - mc;
            float nj = bc - b[k];
            bool valid = (dj > 0.f) || (dj == 0.f && nj < 0.f);
            // dj==0, nj<0 -> -inf (equal slope, strictly above: take immediately)
            float x = valid ? __fdividef(nj, dj) : F_INF;
            if (x < bx || (x == bx && m[k] > bm)) { bx = x; bm = m[k]; bb = b[k]; }
        }
#pragma unroll
        for (int o = 16; o; o >>= 1) {
            float ox = __shfl_xor_sync(0xFFFFFFFFu, bx, o);
            float om = __shfl_xor_sync(0xFFFFFFFFu, bm, o);
            float ob = __shfl_xor_sync(0xFFFFFFFFu, bb, o);
            if (ox < bx || (ox == bx && om > bm)) { bx = ox; bm = om; bb = ob; }
        }
        bx = __shfl_sync(0xFFFFFFFFu, bx, 0);
        bm = __shfl_sync(0xFFFFFFFFu, bm, 0);
        bb = __shfl_sync(0xFFFFFFFFu, bb, 0);
        if (!(bx < F_INF)) break;   // no valid candidate -> envelope complete
        mc = bm; bc = bb;
    }
    if (lane == 0) g_cnt[branch][d][w] = cnt;
}

// ───────────────────────── eval kernel ─────────────────────────
// 128 CTAs: blockIdx = branch (bx>>6) x batch-group of 16 (bx&63).
// Threads: tb = t&15 (batch in group), ts = t>>4 (w-slice of 16 w's).
// Layer dependency resolved fully inside the CTA (shfl + smem) — no atomics,
// no grid barrier, no init kernel.
__global__ void __launch_bounds__(256, 1) eval_kernel(
    const float* __restrict__ val, float* __restrict__ out) {
    __shared__ float2 s_hull[HC][WDIM];   // 40 KB
    __shared__ int    s_cnt[WDIM];
    __shared__ float  s_red[8][16];
    __shared__ float  s_q[16];

    const int t      = threadIdx.x;
    const int branch = blockIdx.x >> 6;
    const int grp    = blockIdx.x & 63;
    const int tb     = t & 15;
    const int ts     = t >> 4;

    float q = val[grp * 16 + tb];

    for (int d = 0; d < DEPTH; ++d) {
        // Stage this layer's compact hulls: thread t stages w = t (coalesced).
        int c = g_cnt[branch][d][t];
        s_cnt[t] = c;
        int cl = min(c, HC);
        for (int k = 0; k < cl; k++)
            s_hull[k][t] = g_hullc[branch][d][k][t];
        __syncthreads();

        float vmin = F_INF;
        for (int j = 0; j < 16; j++) {
            int w  = ts * 16 + j;          // lanes 0-15 of a warp share w -> LDS broadcast
            int cw = s_cnt[w];
            float vmax = -F_INF;
            if (cw <= HC) {
                for (int k = 0; k < cw; k++) {
                    float2 l = s_hull[k][w];
                    vmax = fmaxf(vmax, fmaf(q, l.x, l.y));
                }
            } else {                       // rare fallback: oversized hull
                const float2* hp = &g_hull[branch][d][w][0];
                for (int k = 0; k < cw; k++) {
                    float2 l = __ldg(hp + k);
                    vmax = fmaxf(vmax, fmaf(q, l.x, l.y));
                }
            }
            vmin = fminf(vmin, vmax);
        }

        // Reduce min over the 16 w-slices for each batch tb.
        vmin = fminf(vmin, __shfl_xor_sync(0xFFFFFFFFu, vmin, 16));
        if ((t & 31) < 16) s_red[t >> 5][t & 15] = vmin;
        __syncthreads();
        if (t < 16) {
            float acc = s_red[0][t];
#pragma unroll
            for (int r = 1; r < 8; r++) acc = fminf(acc, s_red[r][t]);
            s_q[t] = acc;
        }
        __syncthreads();                   // also guards s_hull reuse next layer
        q = s_q[tb];
    }

    if (t < 16)
        out[branch * BATCH + grp * 16 + t] = q;
}

extern "C" void kernel_launch(void* const* d_in, const int* in_sizes, int n_in,
                              void* d_out, int out_size) {
    const float* val = (const float*)d_in[0];
    const float* M1  = (const float*)d_in[1];
    const float* B1  = (const float*)d_in[2];
    const float* M2  = (const float*)d_in[3];
    const float* B2  = (const float*)d_in[4];
    float* out = (float*)d_out;

    hull_kernel<<<(2 * DEPTH * WDIM * 32) / 256, 256>>>(M1, B1, M2, B2);
    eval_kernel<<<128, 256>>>(val, out);
}

// round 4
// speedup vs baseline: 6.5927x; 2.2845x over previous
#include <cuda_runtime.h>

#define BATCH   1024
#define WDIM    256
#define HDIM    256
#define DEPTH   8
#define HMAX    256     // absolute worst-case hull size
#define HP      16      // padded fast-path hull size (Gaussian data: ~6-10 lines)

#define F_INF   __int_as_float(0x7F800000)
#define F_NINF  __int_as_float(0xFF800000)

// Static device scratch (allocation-free rule).
__device__ float2 g_hull [2][DEPTH][WDIM][HMAX];  // full hulls (rare fallback)
__device__ float4 g_hullp[2][DEPTH][WDIM][HP/2];  // padded: 16 lines = 128B per w
__device__ int    g_cnt  [2][DEPTH][WDIM];

// Monotone float -> uint key (uint order == float order, incl. +-inf).
__device__ __forceinline__ unsigned fkey(float f) {
    unsigned u = __float_as_uint(f);
    return (u & 0x80000000u) ? ~u : (u | 0x80000000u);
}

// ───────────────────────── hull kernel ─────────────────────────
// One warp per envelope (branch, d, w): gift-wrap the upper envelope of the
// 256 lines y = m*q + b. fp32 only; warp argmin via REDUX on ordered keys.
__global__ void __launch_bounds__(256) hull_kernel(
    const float* __restrict__ M1, const float* __restrict__ B1,
    const float* __restrict__ M2, const float* __restrict__ B2) {
    const int gw     = (blockIdx.x * blockDim.x + threadIdx.x) >> 5;  // 0..4095
    const int lane   = threadIdx.x & 31;
    const int branch = gw >> 11;
    const int d      = (gw >> 8) & 7;
    const int w      = gw & 255;

    const float* Mp = (branch ? M2 : M1) + (size_t)((d << 8) + w) * HDIM;
    const float* Bp = (branch ? B2 : B1) + (size_t)((d << 8) + w) * HDIM;

    float m[8], b[8];
#pragma unroll
    for (int k = 0; k < 8; k++) {
        m[k] = Mp[lane + (k << 5)];
        b[k] = Bp[lane + (k << 5)];
    }

    // Start line: (approximately) min slope. A dominated equal-slope start
    // self-corrects on the first step (x = -inf candidate), so no tie-break.
    float mc = m[0], bc = b[0];
#pragma unroll
    for (int k = 1; k < 8; k++)
        if (m[k] < mc || (m[k] == mc && b[k] > bc)) { mc = m[k]; bc = b[k]; }
    {
        unsigned mk = __reduce_min_sync(0xFFFFFFFFu, fkey(mc));
        unsigned bal = __ballot_sync(0xFFFFFFFFu, fkey(mc) == mk);
        int src = __ffs(bal) - 1;
        mc = __shfl_sync(0xFFFFFFFFu, mc, src);
        bc = __shfl_sync(0xFFFFFFFFu, bc, src);
    }

    float2* hf = &g_hull[branch][d][w][0];
    float2* hp = (float2*)&g_hullp[branch][d][w][0];
    const unsigned KEY_INF = fkey(F_INF);

    int cnt = 0;
    for (int step = 0; step < HMAX; ++step) {
        if (lane == 0) {
            hf[cnt] = make_float2(mc, bc);
            if (cnt < HP) hp[cnt] = make_float2(mc, bc);
        }
        cnt++;

        // Per-lane best candidate: smallest crossing x among overtaking lines.
        // dj==0 && nj<0 (equal slope, strictly above) -> x = -inf via fdividef.
        float bx = F_INF, bm = 0.f, bb = 0.f;
#pragma unroll
        for (int k = 0; k < 8; k++) {
            float dj = m[k] - mc;
            float nj = bc - b[k];
            bool valid = (dj > 0.f) || (dj == 0.f && nj < 0.f);
            float x = valid ? __fdividef(nj, dj) : F_INF;
            if (x < bx) { bx = x; bm = m[k]; bb = b[k]; }
        }
        // Warp argmin: single REDUX on ordered key + leader broadcast.
        unsigned wk  = __reduce_min_sync(0xFFFFFFFFu, fkey(bx));
        if (wk >= KEY_INF) break;                     // envelope complete
        unsigned bal = __ballot_sync(0xFFFFFFFFu, fkey(bx) == wk);
        int src = __ffs(bal) - 1;
        mc = __shfl_sync(0xFFFFFFFFu, bm, src);
        bc = __shfl_sync(0xFFFFFFFFu, bb, src);
    }

    // Pad the compact hull to HP lines with (0, -inf): neutral for max.
    for (int k = cnt + lane; k < HP; k += 32)
        hp[k] = make_float2(0.f, F_NINF);
    if (lane == 0) g_cnt[branch][d][w] = cnt;
}

// ───────────────────────── eval kernel ─────────────────────────
// 128 independent CTAs: blockIdx = branch (bx>>6) x batch-group of 16 (bx&63).
// 512 threads: qg = t&3 (batch quad -> 4 q's in registers), ws = t>>2 (2 w's).
// Per layer: fully unrolled 16-line hull eval straight from L1 (no staging),
// then in-CTA min-reduction over w (shfl + smem). No atomics, no grid sync.
__global__ void __launch_bounds__(512, 1) eval_kernel(
    const float* __restrict__ val, float* __restrict__ out) {
    __shared__ float s_red[16][16];   // [warp][batch-in-group]
    __shared__ float s_q[16];

    const int t      = threadIdx.x;
    const int branch = blockIdx.x >> 6;
    const int grp    = blockIdx.x & 63;
    const int qg     = t & 3;
    const int ws     = t >> 2;        // 0..127
    const int warp   = t >> 5;
    const int lane   = t & 31;

    float q[4];
#pragma unroll
    for (int i = 0; i < 4; i++) q[i] = val[grp * 16 + qg * 4 + i];

    for (int d = 0; d < DEPTH; ++d) {
        float vmin[4] = {F_INF, F_INF, F_INF, F_INF};
#pragma unroll
        for (int wo = 0; wo < 2; wo++) {
            const int w = ws * 2 + wo;
            const float4* hp = &g_hullp[branch][d][w][0];
            float vmax[4] = {F_NINF, F_NINF, F_NINF, F_NINF};
#pragma unroll
            for (int k8 = 0; k8 < HP / 2; k8++) {
                float4 p = __ldg(hp + k8);            // 2 lines per 16B load
#pragma unroll
                for (int i = 0; i < 4; i++)
                    vmax[i] = fmaxf(vmax[i],
                                    fmaxf(fmaf(q[i], p.x, p.y),
                                          fmaf(q[i], p.z, p.w)));
            }
            int cw = __ldg(&g_cnt[branch][d][w]);
            if (cw > HP) {                            // rare oversized hull
                const float2* fp = &g_hull[branch][d][w][0];
                for (int k = HP; k < cw; k++) {
                    float2 l = __ldg(fp + k);
#pragma unroll
                    for (int i = 0; i < 4; i++)
                        vmax[i] = fmaxf(vmax[i], fmaf(q[i], l.x, l.y));
                }
            }
#pragma unroll
            for (int i = 0; i < 4; i++) vmin[i] = fminf(vmin[i], vmax[i]);
        }

        // Intra-warp: min across the 8 w-slices sharing each batch quad.
#pragma unroll
        for (int o = 4; o <= 16; o <<= 1)
#pragma unroll
            for (int i = 0; i < 4; i++)
                vmin[i] = fminf(vmin[i], __shfl_xor_sync(0xFFFFFFFFu, vmin[i], o));
        // Lanes 0-3 now hold the warp result for batch quad = lane.
        if (lane < 4)
#pragma unroll
            for (int i = 0; i < 4; i++) s_red[warp][lane * 4 + i] = vmin[i];
        __syncthreads();
        if (t < 16) {
            float acc = s_red[0][t];
#pragma unroll
            for (int r = 1; r < 16; r++) acc = fminf(acc, s_red[r][t]);
            s_q[t] = acc;
        }
        __syncthreads();
#pragma unroll
        for (int i = 0; i < 4; i++) q[i] = s_q[qg * 4 + i];
    }

    if (t < 16)
        out[branch * BATCH + grp * 16 + t] = s_q[t];
}

extern "C" void kernel_launch(void* const* d_in, const int* in_sizes, int n_in,
                              void* d_out, int out_size) {
    const float* val = (const float*)d_in[0];
    const float* M1  = (const float*)d_in[1];
    const float* B1  = (const float*)d_in[2];
    const float* M2  = (const float*)d_in[3];
    const float* B2  = (const float*)d_in[4];
    float* out = (float*)d_out;

    hull_kernel<<<(2 * DEPTH * WDIM * 32) / 256, 256>>>(M1, B1, M2, B2);
    eval_kernel<<<128, 512>>>(val, out);
}